// round 1
// baseline (speedup 1.0000x reference)
#include <cuda_runtime.h>
#include <cstdint>

#define EMB 128
#define NR 6
#define TILE_E 128
#define THREADS 256

// Precomputed table @ W_block projections (device scratch; no allocation).
__device__ float g_Tsrc[96 * EMB];
__device__ float g_Tdst[96 * EMB];
__device__ float g_Tstep[20 * EMB];
__device__ float g_Teq[2 * EMB];

__device__ __forceinline__ float silu_f(float x) {
    return x / (1.0f + __expf(-x));
}

__device__ __forceinline__ unsigned long long pack2(float lo, float hi) {
    unsigned long long r;
    asm("mov.b64 %0, {%1, %2};" : "=l"(r) : "f"(lo), "f"(hi));
    return r;
}
__device__ __forceinline__ void unpack2(unsigned long long v, float& lo, float& hi) {
    asm("mov.b64 {%0, %1}, %2;" : "=f"(lo), "=f"(hi) : "l"(v));
}
__device__ __forceinline__ void fma2(unsigned long long& acc, unsigned long long a, unsigned long long b) {
    asm("fma.rn.f32x2 %0, %1, %2, %0;" : "+l"(acc) : "l"(a), "l"(b));
}

// ---------------------------------------------------------------------------
// Kernel 1: precompute T_x = table @ W_block (folding bias b into T_eq).
// grid = 96 + 96 + 20 + 2 = 214 rows, 128 threads (one per output channel).
// ---------------------------------------------------------------------------
__global__ void precompute_kernel(const float* __restrict__ emb_table,
                                  const float* __restrict__ step_table,
                                  const float* __restrict__ equiv_table,
                                  const float* __restrict__ W,
                                  const float* __restrict__ b)
{
    __shared__ float in[EMB];
    int r = blockIdx.x;
    int c = threadIdx.x;

    const float* src_row;
    float* out_row;
    const float* Wblk;
    bool addb = false;

    if (r < 96)       { src_row = emb_table  + r * EMB;         out_row = g_Tsrc  + r * EMB;         Wblk = W + 0 * EMB * EMB; }
    else if (r < 192) { src_row = emb_table  + (r - 96) * EMB;  out_row = g_Tdst  + (r - 96) * EMB;  Wblk = W + 1 * EMB * EMB; }
    else if (r < 212) { src_row = step_table + (r - 192) * EMB; out_row = g_Tstep + (r - 192) * EMB; Wblk = W + 3 * EMB * EMB; }
    else              { src_row = equiv_table+ (r - 212) * EMB; out_row = g_Teq   + (r - 212) * EMB; Wblk = W + 4 * EMB * EMB; addb = true; }

    in[c] = src_row[c];
    __syncthreads();

    float acc = addb ? b[c] : 0.0f;
    #pragma unroll 8
    for (int k = 0; k < EMB; k++)
        acc += in[k] * Wblk[k * EMB + c];
    out_row[c] = acc;
}

// ---------------------------------------------------------------------------
// Kernel 2: main per-edge kernel.
//   m[e,c] = silu( rbf_a[e,:] @ W2[:,c] + Tsrc[Z[src]] + Tdst[Z[dst]]
//                  + Tstep[step[src]] + Teq[equiv] )        (bias folded in Teq)
// One CTA = 128 edges x 128 channels. SGEMM with fp32x2 packed FMAs.
// Dynamic smem: Ws[128][128] + As[128][128] + 4*int[128]  = 133120 B
// ---------------------------------------------------------------------------
extern __shared__ float smem_raw[];

__global__ __launch_bounds__(THREADS, 1)
void edge_kernel(const int* __restrict__ Z, const int* __restrict__ stepA,
                 const int* __restrict__ src, const int* __restrict__ dst,
                 const int* __restrict__ equiv,
                 const float* __restrict__ rbf,
                 const float* __restrict__ W_rbf, const float* __restrict__ b_rbf,
                 const float* __restrict__ W2,
                 float* __restrict__ out, int E)
{
    float (*Ws)[EMB]    = (float(*)[EMB])smem_raw;                       // Ws[k][c]
    float (*As)[TILE_E] = (float(*)[TILE_E])(smem_raw + EMB * EMB);      // As[k][e]
    int* s_zs = (int*)(smem_raw + 2 * EMB * EMB);
    int* s_zd = s_zs + TILE_E;
    int* s_st = s_zd + TILE_E;
    int* s_eq = s_st + TILE_E;

    const int tid = threadIdx.x;
    const int ebase = blockIdx.x * TILE_E;

    // ---- load W2 (128x128 fp32) into smem, coalesced float4 ----
    {
        const float4* Wg = (const float4*)W2;
        float4* Wsm = (float4*)&Ws[0][0];
        #pragma unroll
        for (int i = tid; i < EMB * EMB / 4; i += THREADS) Wsm[i] = Wg[i];
    }

    // ---- phase 2: rbf_a tile (silu(rbf @ W_rbf + b_rbf)) + edge index gather ----
    {
        const int e = tid >> 1;            // 0..127
        const int kh = (tid & 1) * 64;     // channel half
        const int ge = ebase + e;
        const bool valid = (ge < E);
        float r0 = 0, r1 = 0, r2 = 0, r3 = 0, r4 = 0, r5 = 0;
        if (valid) {
            const float* rp = rbf + (size_t)ge * NR;
            r0 = rp[0]; r1 = rp[1]; r2 = rp[2]; r3 = rp[3]; r4 = rp[4]; r5 = rp[5];
            if ((tid & 1) == 0) {
                int s = src[ge], dd = dst[ge];
                s_zs[e] = Z[s];
                s_zd[e] = Z[dd];
                s_st[e] = stepA[s];
                s_eq[e] = equiv[ge];
            }
        }
        #pragma unroll 8
        for (int kk = 0; kk < 64; kk++) {
            int k = kh + kk;
            float z = b_rbf[k]
                    + r0 * W_rbf[0 * EMB + k] + r1 * W_rbf[1 * EMB + k]
                    + r2 * W_rbf[2 * EMB + k] + r3 * W_rbf[3 * EMB + k]
                    + r4 * W_rbf[4 * EMB + k] + r5 * W_rbf[5 * EMB + k];
            As[k][e] = valid ? silu_f(z) : 0.0f;
        }
    }
    __syncthreads();

    // ---- phase 3: SGEMM  (8 edges x 8 channels per thread, fp32x2 packed) ----
    const int er = tid >> 4;       // 0..15
    const int cr = tid & 15;       // 0..15
    const int e0 = er * 8;
    const int c0 = cr * 8;

    unsigned long long acc[8][4];
    #pragma unroll
    for (int i = 0; i < 8; i++)
        #pragma unroll
        for (int j = 0; j < 4; j++) acc[i][j] = 0ull;

    #pragma unroll 4
    for (int k = 0; k < EMB; k++) {
        float4 a0 = *(const float4*)&As[k][e0];
        float4 a1 = *(const float4*)&As[k][e0 + 4];
        float4 b0 = *(const float4*)&Ws[k][c0];
        float4 b1 = *(const float4*)&Ws[k][c0 + 4];
        unsigned long long bp0 = pack2(b0.x, b0.y);
        unsigned long long bp1 = pack2(b0.z, b0.w);
        unsigned long long bp2 = pack2(b1.x, b1.y);
        unsigned long long bp3 = pack2(b1.z, b1.w);
        float av[8] = {a0.x, a0.y, a0.z, a0.w, a1.x, a1.y, a1.z, a1.w};
        #pragma unroll
        for (int i = 0; i < 8; i++) {
            unsigned long long ap = pack2(av[i], av[i]);
            fma2(acc[i][0], ap, bp0);
            fma2(acc[i][1], ap, bp1);
            fma2(acc[i][2], ap, bp2);
            fma2(acc[i][3], ap, bp3);
        }
    }

    // ---- epilogue: add 4 gathered table rows, silu, store ----
    #pragma unroll
    for (int i = 0; i < 8; i++) {
        const int e = e0 + i;
        const int ge = ebase + e;
        if (ge < E) {
            const int zs = s_zs[e], zd = s_zd[e], st = s_st[e], eq = s_eq[e];
            const float4* ts = (const float4*)(g_Tsrc  + zs * EMB + c0);
            const float4* td = (const float4*)(g_Tdst  + zd * EMB + c0);
            const float4* tt = (const float4*)(g_Tstep + st * EMB + c0);
            const float4* te = (const float4*)(g_Teq   + eq * EMB + c0);
            float4* op = (float4*)(out + (size_t)ge * EMB + c0);
            #pragma unroll
            for (int h = 0; h < 2; h++) {
                float4 s1 = ts[h], s2 = td[h], s3 = tt[h], s4 = te[h];
                float lo0, hi0, lo1, hi1;
                unpack2(acc[i][h * 2 + 0], lo0, hi0);
                unpack2(acc[i][h * 2 + 1], lo1, hi1);
                float4 v;
                v.x = silu_f(lo0 + s1.x + s2.x + s3.x + s4.x);
                v.y = silu_f(hi0 + s1.y + s2.y + s3.y + s4.y);
                v.z = silu_f(lo1 + s1.z + s2.z + s3.z + s4.z);
                v.w = silu_f(hi1 + s1.w + s2.w + s3.w + s4.w);
                op[h] = v;
            }
        }
    }
}

// ---------------------------------------------------------------------------
// Kernel 3: rbf_env = envelope(x)[:,None] * sin(x*freqs)/x
//   p = 6: env = 1/x - 28 x^5 + 48 x^6 - 21 x^7
// ---------------------------------------------------------------------------
__global__ void rbf_env_kernel(const float* __restrict__ dvec, float* __restrict__ out, int E)
{
    int e = blockIdx.x * blockDim.x + threadIdx.x;
    if (e >= E) return;
    float x = dvec[e] * 0.2f;                  // d / CUTOFF
    float inv = 1.0f / x;
    float x2 = x * x;
    float x4 = x2 * x2;
    float x5 = x4 * x;
    float env = inv + x5 * (-28.0f + x * (48.0f + x * (-21.0f)));
    float coef = env * inv;
    float* o = out + (size_t)e * NR;
    const float PI = 3.14159265358979323846f;
    #pragma unroll
    for (int j = 0; j < NR; j++) {
        o[j] = coef * sinf(x * (PI * (float)(j + 1)));
    }
}

// ---------------------------------------------------------------------------
extern "C" void kernel_launch(void* const* d_in, const int* in_sizes, int n_in,
                              void* d_out, int out_size)
{
    const int*   Z          = (const int*)d_in[0];
    const int*   stepA      = (const int*)d_in[1];
    const int*   src        = (const int*)d_in[2];
    const int*   dst        = (const int*)d_in[3];
    const int*   equiv      = (const int*)d_in[4];
    const float* rbf        = (const float*)d_in[5];
    const float* dvec       = (const float*)d_in[6];
    const float* emb_table  = (const float*)d_in[7];
    const float* step_table = (const float*)d_in[8];
    const float* equiv_tab  = (const float*)d_in[9];
    const float* W_rbf      = (const float*)d_in[10];
    const float* b_rbf      = (const float*)d_in[11];
    const float* W          = (const float*)d_in[12];
    const float* b          = (const float*)d_in[13];
    float* out = (float*)d_out;

    const int E = in_sizes[2];   // number of edges (src size)

    const int smem_bytes = (2 * EMB * EMB) * (int)sizeof(float) + 4 * TILE_E * (int)sizeof(int);
    cudaFuncSetAttribute(edge_kernel, cudaFuncAttributeMaxDynamicSharedMemorySize, smem_bytes);

    precompute_kernel<<<214, 128>>>(emb_table, step_table, equiv_tab, W, b);

    const int tiles = (E + TILE_E - 1) / TILE_E;
    edge_kernel<<<tiles, THREADS, smem_bytes>>>(Z, stepA, src, dst, equiv,
                                                rbf, W_rbf, b_rbf,
                                                W + 2 * EMB * EMB, out, E);

    rbf_env_kernel<<<(E + 255) / 256, 256>>>(dvec, out + (size_t)E * EMB, E);
}

// round 4
// speedup vs baseline: 1.7874x; 1.7874x over previous
#include <cuda_runtime.h>
#include <cuda_bf16.h>
#include <cstdint>

#define EMB 128
#define NR 6
#define SA 272          // A/B smem row stride in bytes (136 bf16)
#define SS 132          // Sum4 row stride in floats

// Precomputed table @ W_block projections: rows 0-95 Tsrc, 96-191 Tdst,
// 192-211 Tstep, 212-213 Teq (+bias folded into Teq rows).
__device__ float g_T[214 * EMB];

__device__ __forceinline__ uint32_t smem_u32(const void* p) {
    uint32_t a;
    asm("{ .reg .u64 t; cvta.to.shared.u64 t, %1; cvt.u32.u64 %0, t; }" : "=r"(a) : "l"(p));
    return a;
}
__device__ __forceinline__ float silu_f(float x) {
    return __fdividef(x, 1.0f + __expf(-x));
}
__device__ __forceinline__ void ldsm4(uint32_t* r, uint32_t addr) {
    asm volatile("ldmatrix.sync.aligned.m8n8.x4.shared.b16 {%0,%1,%2,%3}, [%4];"
                 : "=r"(r[0]), "=r"(r[1]), "=r"(r[2]), "=r"(r[3]) : "r"(addr));
}
__device__ __forceinline__ void ldsm4t(uint32_t* r, uint32_t addr) {
    asm volatile("ldmatrix.sync.aligned.m8n8.x4.trans.shared.b16 {%0,%1,%2,%3}, [%4];"
                 : "=r"(r[0]), "=r"(r[1]), "=r"(r[2]), "=r"(r[3]) : "r"(addr));
}
__device__ __forceinline__ void mma_bf16(float* d, const uint32_t* a, const uint32_t* b) {
    asm volatile("mma.sync.aligned.m16n8k16.row.col.f32.bf16.bf16.f32 "
                 "{%0,%1,%2,%3}, {%4,%5,%6,%7}, {%8,%9}, {%0,%1,%2,%3};"
                 : "+f"(d[0]), "+f"(d[1]), "+f"(d[2]), "+f"(d[3])
                 : "r"(a[0]), "r"(a[1]), "r"(a[2]), "r"(a[3]), "r"(b[0]), "r"(b[1]));
}

// ---------------------------------------------------------------------------
// Kernel 1: g_T = tables @ W_blocks (bias folded into Teq rows)
// ---------------------------------------------------------------------------
__global__ void precompute_kernel(const float* __restrict__ emb_table,
                                  const float* __restrict__ step_table,
                                  const float* __restrict__ equiv_table,
                                  const float* __restrict__ W,
                                  const float* __restrict__ b)
{
    __shared__ float in[EMB];
    int r = blockIdx.x, c = threadIdx.x;
    const float* srow; const float* Wb; bool addb = false;
    if (r < 96)       { srow = emb_table + r * EMB;           Wb = W; }
    else if (r < 192) { srow = emb_table + (r - 96) * EMB;    Wb = W + EMB * EMB; }
    else if (r < 212) { srow = step_table + (r - 192) * EMB;  Wb = W + 3 * EMB * EMB; }
    else              { srow = equiv_table + (r - 212) * EMB; Wb = W + 4 * EMB * EMB; addb = true; }
    in[c] = srow[c];
    __syncthreads();
    float a0 = 0, a1 = 0, a2 = 0, a3 = 0;
    #pragma unroll
    for (int k = 0; k < EMB; k += 4) {
        a0 = fmaf(in[k + 0], Wb[(k + 0) * EMB + c], a0);
        a1 = fmaf(in[k + 1], Wb[(k + 1) * EMB + c], a1);
        a2 = fmaf(in[k + 2], Wb[(k + 2) * EMB + c], a2);
        a3 = fmaf(in[k + 3], Wb[(k + 3) * EMB + c], a3);
    }
    g_T[r * EMB + c] = (a0 + a1) + (a2 + a3) + (addb ? b[c] : 0.0f);
}

// ---------------------------------------------------------------------------
// Kernel 2: persistent fused edge kernel (mma.sync bf16 hi/lo 3-pass GEMM)
// smem layout (bytes):
//   0      Ahi   34816   (bf16 [128 e][136 k])
//   34816  Alo   34816
//   69632  Bhi   34816   (bf16 [128 k][136 n])
//   104448 Blo   34816
//   139264 Sum4  67584   (f32 [128 e][132 c])
//   206848 Wr     4096   (f32 [128 k][8])
//   210944 sidx   2048   (int [4][128])
//   total 212992
// ---------------------------------------------------------------------------
__global__ __launch_bounds__(256, 1)
void edge_kernel(const int* __restrict__ Z, const int* __restrict__ stepA,
                 const int* __restrict__ src, const int* __restrict__ dst,
                 const int* __restrict__ equiv,
                 const float* __restrict__ rbf, const float* __restrict__ dvec,
                 const float* __restrict__ W_rbf, const float* __restrict__ b_rbf,
                 const float* __restrict__ W2,
                 float* __restrict__ out, int E, int tiles)
{
    extern __shared__ char sm[];
    char*  const Ahi  = sm;
    char*  const Alo  = sm + 34816;
    char*  const Bhi  = sm + 69632;
    char*  const Blo  = sm + 104448;
    float* const Sum4 = (float*)(sm + 139264);
    float* const Wr   = (float*)(sm + 206848);
    int*   const sidx = (int*)(sm + 210944);

    const int tid  = threadIdx.x;
    const int wid  = tid >> 5;
    const int lane = tid & 31;

    // ---- one-time setup ----
    for (int idx = tid; idx < EMB * EMB; idx += 256) {
        int k = idx >> 7, n = idx & 127;
        float w = W2[idx];                        // W2[k][n]
        __nv_bfloat16 h = __float2bfloat16(w);
        float l = w - __bfloat162float(h);
        *(__nv_bfloat16*)(Bhi + k * SA + n * 2) = h;
        *(__nv_bfloat16*)(Blo + k * SA + n * 2) = __float2bfloat16(l);
    }
    for (int i = tid; i < EMB * 8; i += 256) {
        int k = i >> 3, j = i & 7;
        Wr[i] = (j < 6) ? W_rbf[j * EMB + k] : (j == 6 ? b_rbf[k] : 0.0f);
    }
    const float4 te0 = *(const float4*)&g_T[212 * EMB + lane * 4];
    const float4 te1 = *(const float4*)&g_T[213 * EMB + lane * 4];
    __syncthreads();

    const int wm = wid & 3, wn = wid >> 2;
    const int m0 = wm * 32, nb = wn * 64;
    const uint32_t lmoff = (uint32_t)((lane & 15) * SA + (lane >> 4) * 16);
    const uint32_t Ahi_u = smem_u32(Ahi), Alo_u = smem_u32(Alo);
    const uint32_t Bhi_u = smem_u32(Bhi), Blo_u = smem_u32(Blo);
    float* const envo = out + (size_t)E * EMB;

    for (int t = blockIdx.x; t < tiles; t += gridDim.x) {
        const int ebase = t * 128;

        // ---- P1: indices (tid<128) + rbf_env (tid>=128) ----
        if (tid < 128) {
            const int ge = ebase + tid;
            int zs = 0, zd = 0, st = 0, eq = 0;
            if (ge < E) {
                int s = src[ge], dd = dst[ge];
                zs = Z[s]; zd = Z[dd]; st = stepA[s]; eq = equiv[ge];
            }
            sidx[tid] = zs; sidx[128 + tid] = zd;
            sidx[256 + tid] = st; sidx[384 + tid] = eq;
        } else {
            const int ge = ebase + tid - 128;
            if (ge < E) {
                float x = dvec[ge] * 0.2f;
                float inv = 1.0f / x;
                float x2 = x * x;
                float x5 = x2 * x2 * x;
                float env = inv + x5 * (-28.0f + x * (48.0f + x * (-21.0f)));
                float coef = env * inv;
                const float PI = 3.14159265358979323846f;
                float* o = envo + (size_t)ge * NR;
                #pragma unroll
                for (int j = 0; j < NR; j++) o[j] = coef * sinf(x * (PI * (float)(j + 1)));
            }
        }
        __syncthreads();

        // ---- P2a: cooperative table-row sums into Sum4 (1 row = 1 LDG.128/warp) ----
        #pragma unroll 4
        for (int i = 0; i < 16; i++) {
            const int e = wid * 16 + i;
            const int zs = sidx[e], zd = sidx[128 + e], st = sidx[256 + e], eq = sidx[384 + e];
            float4 rs = *(const float4*)&g_T[zs * EMB + lane * 4];
            float4 rd = *(const float4*)&g_T[(96 + zd) * EMB + lane * 4];
            float4 rt = *(const float4*)&g_T[(192 + st) * EMB + lane * 4];
            float4 te = eq ? te1 : te0;
            float4 s;
            s.x = (rs.x + rd.x) + (rt.x + te.x);
            s.y = (rs.y + rd.y) + (rt.y + te.y);
            s.z = (rs.z + rd.z) + (rt.z + te.z);
            s.w = (rs.w + rd.w) + (rt.w + te.w);
            *(float4*)&Sum4[e * SS + lane * 4] = s;
        }

        // ---- P2b: A = silu(rbf @ W_rbf + b), bf16 hi/lo row-major into smem ----
        {
            const int e = tid >> 1;
            const int kb = (tid & 1) * 64;
            const int ge = ebase + e;
            float r0 = 0, r1 = 0, r2 = 0, r3 = 0, r4 = 0, r5 = 0;
            if (ge < E) {
                const float* rp = rbf + (size_t)ge * NR;
                r0 = rp[0]; r1 = rp[1]; r2 = rp[2]; r3 = rp[3]; r4 = rp[4]; r5 = rp[5];
            }
            char* ah = Ahi + e * SA + kb * 2;
            char* al = Alo + e * SA + kb * 2;
            #pragma unroll
            for (int kk = 0; kk < 32; kk++) {
                const float* w0 = Wr + (kb + 2 * kk) * 8;
                float4 wa = *(const float4*)(w0);
                float4 wb = *(const float4*)(w0 + 4);
                float4 wc = *(const float4*)(w0 + 8);
                float4 wd = *(const float4*)(w0 + 12);
                float z0 = wb.z + r0 * wa.x + r1 * wa.y + r2 * wa.z + r3 * wa.w + r4 * wb.x + r5 * wb.y;
                float z1 = wd.z + r0 * wc.x + r1 * wc.y + r2 * wc.z + r3 * wc.w + r4 * wd.x + r5 * wd.y;
                float a0 = silu_f(z0);
                float a1 = silu_f(z1);
                __nv_bfloat16 h0 = __float2bfloat16(a0);
                __nv_bfloat16 h1 = __float2bfloat16(a1);
                float l0 = a0 - __bfloat162float(h0);
                float l1 = a1 - __bfloat162float(h1);
                uint32_t hp = ((uint32_t)__bfloat16_as_ushort(h1) << 16) | (uint32_t)__bfloat16_as_ushort(h0);
                uint32_t lp;
                asm("cvt.rn.bf16x2.f32 %0, %1, %2;" : "=r"(lp) : "f"(l1), "f"(l0));
                *(uint32_t*)(ah + kk * 4) = hp;
                *(uint32_t*)(al + kk * 4) = lp;
            }
        }
        __syncthreads();

        // ---- P3: GEMM  D(32x64 per warp) = Ahi*Bhi + Ahi*Blo + Alo*Bhi ----
        float d[2][4][2][4];
        #pragma unroll
        for (int mt = 0; mt < 2; mt++)
            #pragma unroll
            for (int j = 0; j < 4; j++)
                #pragma unroll
                for (int s2 = 0; s2 < 2; s2++)
                    d[mt][j][s2][0] = d[mt][j][s2][1] = d[mt][j][s2][2] = d[mt][j][s2][3] = 0.0f;

        #pragma unroll
        for (int p = 0; p < 3; p++) {
            const uint32_t Au = ((p == 2) ? Alo_u : Ahi_u) + m0 * SA + lmoff;
            const uint32_t Bu = ((p == 1) ? Blo_u : Bhi_u) + nb * 2 + lmoff;
            #pragma unroll
            for (int ks = 0; ks < 8; ks++) {
                uint32_t a[8];
                ldsm4(a + 0, Au + ks * 32);
                ldsm4(a + 4, Au + 16 * SA + ks * 32);
                uint32_t b[16];
                #pragma unroll
                for (int j = 0; j < 4; j++) ldsm4t(b + 4 * j, Bu + ks * 16 * SA + j * 32);
                #pragma unroll
                for (int mt = 0; mt < 2; mt++)
                    #pragma unroll
                    for (int j = 0; j < 4; j++)
                        #pragma unroll
                        for (int s2 = 0; s2 < 2; s2++)
                            mma_bf16(d[mt][j][s2], a + mt * 4, b + 4 * j + 2 * s2);
            }
        }

        // ---- P4: epilogue: + Sum4, silu, direct float2 stores ----
        #pragma unroll
        for (int mt = 0; mt < 2; mt++) {
            const int r = m0 + mt * 16 + (lane >> 2);
            const int ge1 = ebase + r;
            const int ge2 = ge1 + 8;
            const float* S1 = &Sum4[r * SS];
            const float* S2 = &Sum4[(r + 8) * SS];
            #pragma unroll
            for (int j = 0; j < 4; j++)
                #pragma unroll
                for (int s2 = 0; s2 < 2; s2++) {
                    const int c = nb + j * 16 + s2 * 8 + (lane & 3) * 2;
                    const float* dd = d[mt][j][s2];
                    if (ge1 < E) {
                        float2 s = *(const float2*)&S1[c];
                        float2 v;
                        v.x = silu_f(dd[0] + s.x);
                        v.y = silu_f(dd[1] + s.y);
                        *(float2*)&out[(size_t)ge1 * EMB + c] = v;
                    }
                    if (ge2 < E) {
                        float2 s = *(const float2*)&S2[c];
                        float2 v;
                        v.x = silu_f(dd[2] + s.x);
                        v.y = silu_f(dd[3] + s.y);
                        *(float2*)&out[(size_t)ge2 * EMB + c] = v;
                    }
                }
        }
        __syncthreads();
    }
}

// ---------------------------------------------------------------------------
extern "C" void kernel_launch(void* const* d_in, const int* in_sizes, int n_in,
                              void* d_out, int out_size)
{
    const int*   Z          = (const int*)d_in[0];
    const int*   stepA      = (const int*)d_in[1];
    const int*   src        = (const int*)d_in[2];
    const int*   dst        = (const int*)d_in[3];
    const int*   equiv      = (const int*)d_in[4];
    const float* rbf        = (const float*)d_in[5];
    const float* dvec       = (const float*)d_in[6];
    const float* emb_table  = (const float*)d_in[7];
    const float* step_table = (const float*)d_in[8];
    const float* equiv_tab  = (const float*)d_in[9];
    const float* W_rbf      = (const float*)d_in[10];
    const float* b_rbf      = (const float*)d_in[11];
    const float* W          = (const float*)d_in[12];
    const float* b          = (const float*)d_in[13];
    float* out = (float*)d_out;

    const int E = in_sizes[2];
    const int tiles = (E + 127) / 128;

    static int sms = 0;
    if (sms == 0) {
        if (cudaDeviceGetAttribute(&sms, cudaDevAttrMultiProcessorCount, 0) != cudaSuccess || sms <= 0)
            sms = 148;
    }
    const int grid = sms < tiles ? sms : tiles;

    const int smem_bytes = 212992;
    cudaFuncSetAttribute(edge_kernel, cudaFuncAttributeMaxDynamicSharedMemorySize, smem_bytes);

    precompute_kernel<<<214, 128>>>(emb_table, step_table, equiv_tab, W, b);
    edge_kernel<<<grid, 256, smem_bytes>>>(Z, stepA, src, dst, equiv,
                                           rbf, dvec, W_rbf, b_rbf,
                                           W + 2 * EMB * EMB, out, E, tiles);
}